// round 2
// baseline (speedup 1.0000x reference)
#include <cuda_runtime.h>
#include <cuda_bf16.h>
#include <cstdint>

#define N_NODES 50000
#define N_EDGES 1250000
#define N_GRAPHS 128
#define DH 64
#define DOUT 16

// -------- static device scratch (no allocations allowed) --------
__device__ float g_h1[(size_t)N_NODES * DH];
__device__ float g_h2[(size_t)N_NODES * DH];
__device__ float g_pooled[N_GRAPHS * DH];
__device__ float g_counts[N_GRAPHS];
__device__ int   g_deg[N_NODES];
__device__ int   g_roff[N_NODES + 1];
__device__ int   g_cur[N_NODES];
__device__ int   g_csr[N_EDGES];

// ---------------- CSR build ----------------
__global__ void hist_kernel(const int* __restrict__ ei, int ne, int* __restrict__ deg) {
    int t = blockIdx.x * blockDim.x + threadIdx.x;
    if (t < ne) atomicAdd(&deg[__ldg(&ei[ne + t])], 1);
}

// single block, 1024 threads: exclusive scan of deg -> roff (and cursor copy)
__global__ void scan_kernel(const int* __restrict__ deg,
                            int* __restrict__ roff,
                            int* __restrict__ cur) {
    __shared__ int ssum[1024];
    const int PER = (N_NODES + 1023) / 1024;  // 49
    int t = threadIdx.x;
    int base = t * PER;
    int s = 0;
    for (int i = 0; i < PER; ++i) {
        int idx = base + i;
        if (idx < N_NODES) s += deg[idx];
    }
    ssum[t] = s;
    __syncthreads();
    // Hillis-Steele inclusive scan
    for (int off = 1; off < 1024; off <<= 1) {
        int v = (t >= off) ? ssum[t - off] : 0;
        __syncthreads();
        ssum[t] += v;
        __syncthreads();
    }
    int run = ssum[t] - s;  // exclusive prefix
    for (int i = 0; i < PER; ++i) {
        int idx = base + i;
        if (idx < N_NODES) {
            roff[idx] = run;
            cur[idx] = run;
            run += deg[idx];
        }
    }
    if (t == 1023) roff[N_NODES] = ssum[1023];
}

__global__ void fill_kernel(const int* __restrict__ ei, int ne,
                            int* __restrict__ cur, int* __restrict__ csr) {
    int t = blockIdx.x * blockDim.x + threadIdx.x;
    if (t < ne) {
        int d = __ldg(&ei[ne + t]);
        int p = atomicAdd(&cur[d], 1);
        csr[p] = __ldg(&ei[t]);
    }
}

// ------- fused layer: gather-aggregate (CSR) + dual GEMM + bias + ReLU -------
// Block: 256 threads, 64 node-rows per block.
//   Phase A: warp w aggregates rows [8w, 8w+8) into sA (lane owns 2 cols, float2);
//            x tile loaded into sX; Wrel loaded into sW.
//   Phase B: acc += sA @ Wrel; reload sW with Wroot; acc += sX @ Wroot.
//   Epilogue: +bias, optional ReLU, store.
// Dynamic smem: sA[64][68] + sX[64][68] + sW[64][64] = 51200 B -> 4 CTA/SM.
#define LAYER_SMEM ((2 * 64 * 68 + 64 * 64) * 4)

__global__ __launch_bounds__(256, 4)
void layer_kernel(const float* __restrict__ X,
                  const int* __restrict__ csr,
                  const int* __restrict__ roff,
                  const float* __restrict__ Wrel,
                  const float* __restrict__ brel,
                  const float* __restrict__ Wroot,
                  float* __restrict__ out,
                  int do_relu) {
    extern __shared__ float sm[];
    float (*sA)[68] = (float(*)[68])sm;
    float (*sX)[68] = (float(*)[68])(sm + 64 * 68);
    float (*sW)[64] = (float(*)[64])(sm + 2 * 64 * 68);

    int tid = threadIdx.x;
    int rowBase = blockIdx.x * 64;
    int warp = tid >> 5, lane = tid & 31;

    // load Wrel (16KB) as float4
    for (int i = tid; i < 1024; i += 256)
        ((float4*)sW)[i] = ((const float4*)Wrel)[i];

    // load x tile into sX (coalesced float4 rows)
    for (int i = tid; i < 1024; i += 256) {
        int r = i >> 4, c4 = i & 15;
        int g = rowBase + r;
        float4 v = (g < N_NODES) ? ((const float4*)(X + (size_t)g * DH))[c4]
                                 : make_float4(0.f, 0.f, 0.f, 0.f);
        *(float4*)&sX[r][c4 * 4] = v;
    }

    // Phase A: gather-aggregate. Each warp: 8 rows, lane owns cols {2l, 2l+1}.
    const float2* X2 = (const float2*)X;
    #pragma unroll 1
    for (int rr = 0; rr < 8; ++rr) {
        int r = warp * 8 + rr;
        int g = rowBase + r;
        float2 acc = make_float2(0.f, 0.f);
        if (g < N_NODES) {
            int j = __ldg(&roff[g]);
            int end = __ldg(&roff[g + 1]);
            for (; j + 4 <= end; j += 4) {
                int s0 = __ldg(&csr[j]);
                int s1 = __ldg(&csr[j + 1]);
                int s2 = __ldg(&csr[j + 2]);
                int s3 = __ldg(&csr[j + 3]);
                float2 v0 = __ldg(&X2[(size_t)s0 * 32 + lane]);
                float2 v1 = __ldg(&X2[(size_t)s1 * 32 + lane]);
                float2 v2 = __ldg(&X2[(size_t)s2 * 32 + lane]);
                float2 v3 = __ldg(&X2[(size_t)s3 * 32 + lane]);
                acc.x += v0.x; acc.y += v0.y;
                acc.x += v1.x; acc.y += v1.y;
                acc.x += v2.x; acc.y += v2.y;
                acc.x += v3.x; acc.y += v3.y;
            }
            for (; j < end; ++j) {
                int s = __ldg(&csr[j]);
                float2 v = __ldg(&X2[(size_t)s * 32 + lane]);
                acc.x += v.x; acc.y += v.y;
            }
        }
        // contiguous float2 store: conflict-free
        sA[r][lane * 2] = acc.x;
        sA[r][lane * 2 + 1] = acc.y;
    }
    __syncthreads();

    int tx = tid & 15, ty = tid >> 4;
    float acc[4][4] = {};

    // Pass 1: acc += sA @ Wrel
    #pragma unroll 16
    for (int k = 0; k < 64; ++k) {
        float4 bv = *(const float4*)&sW[k][tx * 4];
        float a0 = sA[ty * 4 + 0][k];
        float a1 = sA[ty * 4 + 1][k];
        float a2 = sA[ty * 4 + 2][k];
        float a3 = sA[ty * 4 + 3][k];
        acc[0][0] += a0 * bv.x; acc[0][1] += a0 * bv.y; acc[0][2] += a0 * bv.z; acc[0][3] += a0 * bv.w;
        acc[1][0] += a1 * bv.x; acc[1][1] += a1 * bv.y; acc[1][2] += a1 * bv.z; acc[1][3] += a1 * bv.w;
        acc[2][0] += a2 * bv.x; acc[2][1] += a2 * bv.y; acc[2][2] += a2 * bv.z; acc[2][3] += a2 * bv.w;
        acc[3][0] += a3 * bv.x; acc[3][1] += a3 * bv.y; acc[3][2] += a3 * bv.z; acc[3][3] += a3 * bv.w;
    }
    __syncthreads();

    // reload sW with Wroot
    for (int i = tid; i < 1024; i += 256)
        ((float4*)sW)[i] = ((const float4*)Wroot)[i];
    __syncthreads();

    // Pass 2: acc += sX @ Wroot
    #pragma unroll 16
    for (int k = 0; k < 64; ++k) {
        float4 bv = *(const float4*)&sW[k][tx * 4];
        float a0 = sX[ty * 4 + 0][k];
        float a1 = sX[ty * 4 + 1][k];
        float a2 = sX[ty * 4 + 2][k];
        float a3 = sX[ty * 4 + 3][k];
        acc[0][0] += a0 * bv.x; acc[0][1] += a0 * bv.y; acc[0][2] += a0 * bv.z; acc[0][3] += a0 * bv.w;
        acc[1][0] += a1 * bv.x; acc[1][1] += a1 * bv.y; acc[1][2] += a1 * bv.z; acc[1][3] += a1 * bv.w;
        acc[2][0] += a2 * bv.x; acc[2][1] += a2 * bv.y; acc[2][2] += a2 * bv.z; acc[2][3] += a2 * bv.w;
        acc[3][0] += a3 * bv.x; acc[3][1] += a3 * bv.y; acc[3][2] += a3 * bv.z; acc[3][3] += a3 * bv.w;
    }

    // epilogue
    float4 bb = *(const float4*)&brel[tx * 4];
    #pragma unroll
    for (int i = 0; i < 4; ++i) {
        int g = rowBase + ty * 4 + i;
        if (g < N_NODES) {
            float4 o;
            o.x = acc[i][0] + bb.x;
            o.y = acc[i][1] + bb.y;
            o.z = acc[i][2] + bb.z;
            o.w = acc[i][3] + bb.w;
            if (do_relu) {
                o.x = fmaxf(o.x, 0.f); o.y = fmaxf(o.y, 0.f);
                o.z = fmaxf(o.z, 0.f); o.w = fmaxf(o.w, 0.f);
            }
            *(float4*)(out + (size_t)g * DH + tx * 4) = o;
        }
    }
}

// ---------------- pooling: sums + counts via red.global ----------------
__global__ void pool_kernel(const float* __restrict__ h,
                            const int* __restrict__ batch,
                            float* __restrict__ pooled,
                            float* __restrict__ counts) {
    int tid = blockIdx.x * blockDim.x + threadIdx.x;
    int n = tid >> 4;
    int lane = tid & 15;
    if (n >= N_NODES) return;
    int g = __ldg(&batch[n]);
    float4 v = ((const float4*)(h + (size_t)n * DH))[lane];
    float* dst = pooled + g * DH + lane * 4;
    asm volatile("red.global.add.v4.f32 [%0], {%1,%2,%3,%4};"
                 :: "l"(dst), "f"(v.x), "f"(v.y), "f"(v.z), "f"(v.w)
                 : "memory");
    if (lane == 0) atomicAdd(&counts[g], 1.0f);
}

// --------------- head: out = (pooled/count) @ W_lin + b_lin -------------
__global__ void head_kernel(const float* __restrict__ pooled,
                            const float* __restrict__ counts,
                            const float* __restrict__ Wlin,
                            const float* __restrict__ blin,
                            float* __restrict__ out) {
    int tid = blockIdx.x * blockDim.x + threadIdx.x;
    if (tid >= N_GRAPHS * DOUT) return;
    int g = tid >> 4;
    int o = tid & 15;
    float c = counts[g];
    c = c < 1.0f ? 1.0f : c;
    float s = 0.f;
    #pragma unroll
    for (int k = 0; k < DH; ++k)
        s += pooled[g * DH + k] * Wlin[k * DOUT + o];
    out[g * DOUT + o] = s / c + blin[o];
}

extern "C" void kernel_launch(void* const* d_in, const int* in_sizes, int n_in,
                              void* d_out, int out_size) {
    const float* x      = (const float*)d_in[0];
    const int*   ei     = (const int*)d_in[1];
    const int*   batch  = (const int*)d_in[3];
    const float* Wrel1  = (const float*)d_in[4];
    const float* brel1  = (const float*)d_in[5];
    const float* Wroot1 = (const float*)d_in[6];
    const float* Wrel2  = (const float*)d_in[7];
    const float* brel2  = (const float*)d_in[8];
    const float* Wroot2 = (const float*)d_in[9];
    const float* Wrel3  = (const float*)d_in[10];
    const float* brel3  = (const float*)d_in[11];
    const float* Wroot3 = (const float*)d_in[12];
    const float* Wlin   = (const float*)d_in[13];
    const float* blin   = (const float*)d_in[14];
    float* out = (float*)d_out;

    int ne = in_sizes[1] / 2;

    void *h1_p, *h2_p, *pooled_p, *counts_p, *deg_p, *roff_p, *cur_p, *csr_p;
    cudaGetSymbolAddress(&h1_p, g_h1);
    cudaGetSymbolAddress(&h2_p, g_h2);
    cudaGetSymbolAddress(&pooled_p, g_pooled);
    cudaGetSymbolAddress(&counts_p, g_counts);
    cudaGetSymbolAddress(&deg_p, g_deg);
    cudaGetSymbolAddress(&roff_p, g_roff);
    cudaGetSymbolAddress(&cur_p, g_cur);
    cudaGetSymbolAddress(&csr_p, g_csr);

    float* h1 = (float*)h1_p;
    float* h2 = (float*)h2_p;
    float* pooled = (float*)pooled_p;
    float* counts = (float*)counts_p;
    int* deg = (int*)deg_p;
    int* roff = (int*)roff_p;
    int* cur = (int*)cur_p;
    int* csr = (int*)csr_p;

    static int attr_set = 0;
    if (!attr_set) {
        cudaFuncSetAttribute(layer_kernel,
                             cudaFuncAttributeMaxDynamicSharedMemorySize, LAYER_SMEM);
        attr_set = 1;
    }

    int edgeBlocks = (ne + 255) / 256;
    int gemmBlocks = (N_NODES + 63) / 64;
    int poolBlocks = (N_NODES * 16 + 255) / 256;

    // ---- CSR build ----
    cudaMemsetAsync(deg, 0, N_NODES * sizeof(int), 0);
    hist_kernel<<<edgeBlocks, 256>>>(ei, ne, deg);
    scan_kernel<<<1, 1024>>>(deg, roff, cur);
    fill_kernel<<<edgeBlocks, 256>>>(ei, ne, cur, csr);

    // ---- 3 fused layers ----
    layer_kernel<<<gemmBlocks, 256, LAYER_SMEM>>>(x,  csr, roff, Wrel1, brel1, Wroot1, h1, 1);
    layer_kernel<<<gemmBlocks, 256, LAYER_SMEM>>>(h1, csr, roff, Wrel2, brel2, Wroot2, h2, 1);
    layer_kernel<<<gemmBlocks, 256, LAYER_SMEM>>>(h2, csr, roff, Wrel3, brel3, Wroot3, h1, 0);

    // ---- pooling + head ----
    cudaMemsetAsync(pooled, 0, N_GRAPHS * DH * sizeof(float), 0);
    cudaMemsetAsync(counts, 0, N_GRAPHS * sizeof(float), 0);
    pool_kernel<<<poolBlocks, 256>>>(h1, batch, pooled, counts);
    head_kernel<<<(N_GRAPHS * DOUT + 255) / 256, 256>>>(pooled, counts, Wlin, blin, out);
}

// round 3
// speedup vs baseline: 1.2694x; 1.2694x over previous
#include <cuda_runtime.h>
#include <cuda_bf16.h>
#include <cstdint>

#define N_NODES 50000
#define N_EDGES 1250000
#define N_GRAPHS 128
#define DH 64
#define DOUT 16

// -------- static device scratch --------
__device__ float g_h1[(size_t)N_NODES * DH];
__device__ float g_h2[(size_t)N_NODES * DH];
__device__ int   g_deg[N_NODES];
__device__ int   g_roff[N_NODES + 1];
__device__ int   g_cur[N_NODES];
__device__ int   g_csr[N_EDGES];
__device__ float g_P1[N_GRAPHS * DH];
__device__ float g_P2[N_GRAPHS * DH];
__device__ int   g_nb[N_GRAPHS + 1];

// ---------------- CSR build ----------------
__global__ void hist_k(const int* __restrict__ ei, int ne, int* __restrict__ deg) {
    int t = blockIdx.x * blockDim.x + threadIdx.x;
    if (t < ne) atomicAdd(&deg[__ldg(&ei[ne + t])], 1);
}

__global__ void scan_k(const int* __restrict__ deg,
                       int* __restrict__ roff,
                       int* __restrict__ cur) {
    __shared__ int ssum[1024];
    const int PER = (N_NODES + 1023) / 1024;
    int t = threadIdx.x;
    int base = t * PER;
    int s = 0;
    for (int i = 0; i < PER; ++i) {
        int idx = base + i;
        if (idx < N_NODES) s += deg[idx];
    }
    ssum[t] = s;
    __syncthreads();
    for (int off = 1; off < 1024; off <<= 1) {
        int v = (t >= off) ? ssum[t - off] : 0;
        __syncthreads();
        ssum[t] += v;
        __syncthreads();
    }
    int run = ssum[t] - s;
    for (int i = 0; i < PER; ++i) {
        int idx = base + i;
        if (idx < N_NODES) {
            roff[idx] = run;
            cur[idx] = run;
            run += deg[idx];
        }
    }
    if (t == 1023) roff[N_NODES] = ssum[1023];
}

__global__ void fill_k(const int* __restrict__ ei, int ne,
                       int* __restrict__ cur, int* __restrict__ csr) {
    int t = blockIdx.x * blockDim.x + threadIdx.x;
    if (t < ne) {
        int d = __ldg(&ei[ne + t]);
        int p = atomicAdd(&cur[d], 1);
        csr[p] = __ldg(&ei[t]);
    }
}

// graph node boundaries (batch is sorted)
__global__ void bounds_k(const int* __restrict__ batch, int* __restrict__ nb) {
    int g = threadIdx.x;
    if (g > N_GRAPHS) return;
    if (g == N_GRAPHS) { nb[N_GRAPHS] = N_NODES; return; }
    int lo = 0, hi = N_NODES;
    while (lo < hi) {
        int mid = (lo + hi) >> 1;
        if (__ldg(&batch[mid]) < g) lo = mid + 1; else hi = mid;
    }
    nb[g] = lo;
}

// ------- fused layer: CSR gather + dual GEMM + bias + ReLU -------
#define LAYER_SMEM ((2 * 64 * 68 + 64 * 64) * 4)

__global__ __launch_bounds__(256, 4)
void layer_k(const float* __restrict__ X,
             const int* __restrict__ csr,
             const int* __restrict__ roff,
             const float* __restrict__ Wrel,
             const float* __restrict__ brel,
             const float* __restrict__ Wroot,
             float* __restrict__ out,
             int do_relu) {
    extern __shared__ float sm[];
    float (*sA)[68] = (float(*)[68])sm;
    float (*sX)[68] = (float(*)[68])(sm + 64 * 68);
    float (*sW)[64] = (float(*)[64])(sm + 2 * 64 * 68);
    __shared__ int sRow;

    const unsigned FULL = 0xffffffffu;
    int tid = threadIdx.x;
    int rowBase = blockIdx.x * 64;
    if (tid == 0) sRow = 0;

    for (int i = tid; i < 1024; i += 256)
        ((float4*)sW)[i] = ((const float4*)Wrel)[i];
    for (int i = tid; i < 1024; i += 256) {
        int r = i >> 4, c4 = i & 15;
        int g = rowBase + r;
        float4 v = (g < N_NODES) ? ((const float4*)(X + (size_t)g * DH))[c4]
                                 : make_float4(0.f, 0.f, 0.f, 0.f);
        *(float4*)&sX[r][c4 * 4] = v;
    }
    __syncthreads();

    // gather phase: dynamic row queue, unroll-8 neighbor loads
    int lane = tid & 31;
    const float2* X2 = (const float2*)X;
    for (;;) {
        int r = 0;
        if (lane == 0) r = atomicAdd(&sRow, 1);
        r = __shfl_sync(FULL, r, 0);
        if (r >= 64) break;
        int g = rowBase + r;
        float2 acc = make_float2(0.f, 0.f);
        if (g < N_NODES) {
            int j = __ldg(&roff[g]);
            int end = __ldg(&roff[g + 1]);
            for (; j + 8 <= end; j += 8) {
                int my = (lane < 8) ? __ldg(&csr[j + lane]) : 0;
                int s0 = __shfl_sync(FULL, my, 0);
                int s1 = __shfl_sync(FULL, my, 1);
                int s2 = __shfl_sync(FULL, my, 2);
                int s3 = __shfl_sync(FULL, my, 3);
                int s4 = __shfl_sync(FULL, my, 4);
                int s5 = __shfl_sync(FULL, my, 5);
                int s6 = __shfl_sync(FULL, my, 6);
                int s7 = __shfl_sync(FULL, my, 7);
                float2 v0 = __ldg(&X2[(size_t)s0 * 32 + lane]);
                float2 v1 = __ldg(&X2[(size_t)s1 * 32 + lane]);
                float2 v2 = __ldg(&X2[(size_t)s2 * 32 + lane]);
                float2 v3 = __ldg(&X2[(size_t)s3 * 32 + lane]);
                float2 v4 = __ldg(&X2[(size_t)s4 * 32 + lane]);
                float2 v5 = __ldg(&X2[(size_t)s5 * 32 + lane]);
                float2 v6 = __ldg(&X2[(size_t)s6 * 32 + lane]);
                float2 v7 = __ldg(&X2[(size_t)s7 * 32 + lane]);
                acc.x += v0.x + v1.x + v2.x + v3.x + v4.x + v5.x + v6.x + v7.x;
                acc.y += v0.y + v1.y + v2.y + v3.y + v4.y + v5.y + v6.y + v7.y;
            }
            for (; j + 2 <= end; j += 2) {
                int s0 = __ldg(&csr[j]);
                int s1 = __ldg(&csr[j + 1]);
                float2 v0 = __ldg(&X2[(size_t)s0 * 32 + lane]);
                float2 v1 = __ldg(&X2[(size_t)s1 * 32 + lane]);
                acc.x += v0.x + v1.x;
                acc.y += v0.y + v1.y;
            }
            if (j < end) {
                int s = __ldg(&csr[j]);
                float2 v = __ldg(&X2[(size_t)s * 32 + lane]);
                acc.x += v.x; acc.y += v.y;
            }
        }
        sA[r][lane * 2] = acc.x;
        sA[r][lane * 2 + 1] = acc.y;
    }
    __syncthreads();

    int tx = tid & 15, ty = tid >> 4;
    float acc[4][4] = {};

    #pragma unroll 16
    for (int k = 0; k < 64; ++k) {
        float4 bv = *(const float4*)&sW[k][tx * 4];
        float a0 = sA[ty * 4 + 0][k];
        float a1 = sA[ty * 4 + 1][k];
        float a2 = sA[ty * 4 + 2][k];
        float a3 = sA[ty * 4 + 3][k];
        acc[0][0] += a0 * bv.x; acc[0][1] += a0 * bv.y; acc[0][2] += a0 * bv.z; acc[0][3] += a0 * bv.w;
        acc[1][0] += a1 * bv.x; acc[1][1] += a1 * bv.y; acc[1][2] += a1 * bv.z; acc[1][3] += a1 * bv.w;
        acc[2][0] += a2 * bv.x; acc[2][1] += a2 * bv.y; acc[2][2] += a2 * bv.z; acc[2][3] += a2 * bv.w;
        acc[3][0] += a3 * bv.x; acc[3][1] += a3 * bv.y; acc[3][2] += a3 * bv.z; acc[3][3] += a3 * bv.w;
    }
    __syncthreads();

    for (int i = tid; i < 1024; i += 256)
        ((float4*)sW)[i] = ((const float4*)Wroot)[i];
    __syncthreads();

    #pragma unroll 16
    for (int k = 0; k < 64; ++k) {
        float4 bv = *(const float4*)&sW[k][tx * 4];
        float a0 = sX[ty * 4 + 0][k];
        float a1 = sX[ty * 4 + 1][k];
        float a2 = sX[ty * 4 + 2][k];
        float a3 = sX[ty * 4 + 3][k];
        acc[0][0] += a0 * bv.x; acc[0][1] += a0 * bv.y; acc[0][2] += a0 * bv.z; acc[0][3] += a0 * bv.w;
        acc[1][0] += a1 * bv.x; acc[1][1] += a1 * bv.y; acc[1][2] += a1 * bv.z; acc[1][3] += a1 * bv.w;
        acc[2][0] += a2 * bv.x; acc[2][1] += a2 * bv.y; acc[2][2] += a2 * bv.z; acc[2][3] += a2 * bv.w;
        acc[3][0] += a3 * bv.x; acc[3][1] += a3 * bv.y; acc[3][2] += a3 * bv.z; acc[3][3] += a3 * bv.w;
    }

    float4 bb = *(const float4*)&brel[tx * 4];
    #pragma unroll
    for (int i = 0; i < 4; ++i) {
        int g = rowBase + ty * 4 + i;
        if (g < N_NODES) {
            float4 o;
            o.x = acc[i][0] + bb.x;
            o.y = acc[i][1] + bb.y;
            o.z = acc[i][2] + bb.z;
            o.w = acc[i][3] + bb.w;
            if (do_relu) {
                o.x = fmaxf(o.x, 0.f); o.y = fmaxf(o.y, 0.f);
                o.z = fmaxf(o.z, 0.f); o.w = fmaxf(o.w, 0.f);
            }
            *(float4*)(out + (size_t)g * DH + tx * 4) = o;
        }
    }
}

// ---- P1[g] = sum over edges of graph g of h2[src] (CSR ranges contiguous per graph) ----
__global__ void p1_k(const float* __restrict__ H,
                     const int* __restrict__ csr,
                     const int* __restrict__ roff,
                     const int* __restrict__ nb,
                     float* __restrict__ P1) {
    int g = blockIdx.x >> 2, part = blockIdx.x & 3;
    int ns = __ldg(&nb[g]), neE = __ldg(&nb[g + 1]);
    int es = __ldg(&roff[ns]), ee = __ldg(&roff[neE]);
    long long len = ee - es;
    int start = es + (int)((len * part) >> 2);
    int end = es + (int)((len * (part + 1)) >> 2);
    int grp = threadIdx.x >> 4, lane = threadIdx.x & 15;
    const float4* H4 = (const float4*)H;
    float4 acc = make_float4(0.f, 0.f, 0.f, 0.f);
    int j = start + grp;
    for (; j + 16 < end; j += 32) {
        int s0 = __ldg(&csr[j]);
        int s1 = __ldg(&csr[j + 16]);
        float4 v0 = __ldg(&H4[(size_t)s0 * 16 + lane]);
        float4 v1 = __ldg(&H4[(size_t)s1 * 16 + lane]);
        acc.x += v0.x + v1.x; acc.y += v0.y + v1.y;
        acc.z += v0.z + v1.z; acc.w += v0.w + v1.w;
    }
    if (j < end) {
        int s0 = __ldg(&csr[j]);
        float4 v0 = __ldg(&H4[(size_t)s0 * 16 + lane]);
        acc.x += v0.x; acc.y += v0.y; acc.z += v0.z; acc.w += v0.w;
    }
    __shared__ float sRed[16][68];
    *(float4*)&sRed[grp][lane * 4] = acc;
    __syncthreads();
    if (threadIdx.x < 16) {
        int q = threadIdx.x;
        float4 s = make_float4(0.f, 0.f, 0.f, 0.f);
        #pragma unroll
        for (int t = 0; t < 16; ++t) {
            float4 v = *(float4*)&sRed[t][q * 4];
            s.x += v.x; s.y += v.y; s.z += v.z; s.w += v.w;
        }
        float* dst = P1 + g * DH + q * 4;
        asm volatile("red.global.add.v4.f32 [%0], {%1,%2,%3,%4};"
                     :: "l"(dst), "f"(s.x), "f"(s.y), "f"(s.z), "f"(s.w)
                     : "memory");
    }
}

// ---- P2[g] = sum over nodes of graph g of h2 (node ranges contiguous) ----
__global__ void pool2_k(const float* __restrict__ H,
                        const int* __restrict__ nb,
                        float* __restrict__ P2) {
    int g = blockIdx.x;
    int s = __ldg(&nb[g]), e = __ldg(&nb[g + 1]);
    int grp = threadIdx.x >> 4, lane = threadIdx.x & 15;
    const float4* H4 = (const float4*)H;
    float4 acc = make_float4(0.f, 0.f, 0.f, 0.f);
    for (int r = s + grp; r < e; r += 16) {
        float4 v = __ldg(&H4[(size_t)r * 16 + lane]);
        acc.x += v.x; acc.y += v.y; acc.z += v.z; acc.w += v.w;
    }
    __shared__ float sRed[16][68];
    *(float4*)&sRed[grp][lane * 4] = acc;
    __syncthreads();
    if (threadIdx.x < 16) {
        int q = threadIdx.x;
        float4 sv = make_float4(0.f, 0.f, 0.f, 0.f);
        #pragma unroll
        for (int t = 0; t < 16; ++t) {
            float4 v = *(float4*)&sRed[t][q * 4];
            sv.x += v.x; sv.y += v.y; sv.z += v.z; sv.w += v.w;
        }
        *(float4*)&P2[g * DH + q * 4] = sv;
    }
}

// ---- finale: out[g] = (((P1@Wrel3 + P2@Wroot3)/cnt) + brel3) @ Wlin + blin ----
__global__ void finale_k(const float* __restrict__ P1,
                         const float* __restrict__ P2,
                         const int* __restrict__ nb,
                         const float* __restrict__ Wrel,
                         const float* __restrict__ brel,
                         const float* __restrict__ Wroot,
                         const float* __restrict__ Wlin,
                         const float* __restrict__ blin,
                         float* __restrict__ out) {
    int g = blockIdx.x;
    int c = threadIdx.x;  // 64 threads
    __shared__ float st[64];
    float cnt = fmaxf((float)(nb[g + 1] - nb[g]), 1.0f);
    float t = 0.f;
    #pragma unroll 8
    for (int k = 0; k < 64; ++k)
        t += P1[g * DH + k] * Wrel[k * DH + c] + P2[g * DH + k] * Wroot[k * DH + c];
    st[c] = t / cnt + brel[c];
    __syncthreads();
    if (c < DOUT) {
        float o = blin[c];
        #pragma unroll 8
        for (int k = 0; k < 64; ++k)
            o += st[k] * Wlin[k * DOUT + c];
        out[g * DOUT + c] = o;
    }
}

extern "C" void kernel_launch(void* const* d_in, const int* in_sizes, int n_in,
                              void* d_out, int out_size) {
    const float* x      = (const float*)d_in[0];
    const int*   ei     = (const int*)d_in[1];
    const int*   batch  = (const int*)d_in[3];
    const float* Wrel1  = (const float*)d_in[4];
    const float* brel1  = (const float*)d_in[5];
    const float* Wroot1 = (const float*)d_in[6];
    const float* Wrel2  = (const float*)d_in[7];
    const float* brel2  = (const float*)d_in[8];
    const float* Wroot2 = (const float*)d_in[9];
    const float* Wrel3  = (const float*)d_in[10];
    const float* brel3  = (const float*)d_in[11];
    const float* Wroot3 = (const float*)d_in[12];
    const float* Wlin   = (const float*)d_in[13];
    const float* blin   = (const float*)d_in[14];
    float* out = (float*)d_out;

    int ne = in_sizes[1] / 2;

    void *h1_p, *h2_p, *deg_p, *roff_p, *cur_p, *csr_p, *p1_p, *p2_p, *nb_p;
    cudaGetSymbolAddress(&h1_p, g_h1);
    cudaGetSymbolAddress(&h2_p, g_h2);
    cudaGetSymbolAddress(&deg_p, g_deg);
    cudaGetSymbolAddress(&roff_p, g_roff);
    cudaGetSymbolAddress(&cur_p, g_cur);
    cudaGetSymbolAddress(&csr_p, g_csr);
    cudaGetSymbolAddress(&p1_p, g_P1);
    cudaGetSymbolAddress(&p2_p, g_P2);
    cudaGetSymbolAddress(&nb_p, g_nb);

    float* h1 = (float*)h1_p;
    float* h2 = (float*)h2_p;
    int* deg = (int*)deg_p;
    int* roff = (int*)roff_p;
    int* cur = (int*)cur_p;
    int* csr = (int*)csr_p;
    float* P1 = (float*)p1_p;
    float* P2 = (float*)p2_p;
    int* nb = (int*)nb_p;

    static int attr_set = 0;
    if (!attr_set) {
        cudaFuncSetAttribute(layer_k,
                             cudaFuncAttributeMaxDynamicSharedMemorySize, LAYER_SMEM);
        attr_set = 1;
    }

    int edgeBlocks = (ne + 255) / 256;
    int gemmBlocks = (N_NODES + 63) / 64;

    // CSR build + graph boundaries
    cudaMemsetAsync(deg, 0, N_NODES * sizeof(int), 0);
    hist_k<<<edgeBlocks, 256>>>(ei, ne, deg);
    scan_k<<<1, 1024>>>(deg, roff, cur);
    fill_k<<<edgeBlocks, 256>>>(ei, ne, cur, csr);
    bounds_k<<<1, 256>>>(batch, nb);

    // layers 1-2 (fused gather + GEMM)
    layer_k<<<gemmBlocks, 256, LAYER_SMEM>>>(x,  csr, roff, Wrel1, brel1, Wroot1, h1, 1);
    layer_k<<<gemmBlocks, 256, LAYER_SMEM>>>(h1, csr, roff, Wrel2, brel2, Wroot2, h2, 1);

    // layer 3 folded into pooled space
    cudaMemsetAsync(P1, 0, N_GRAPHS * DH * sizeof(float), 0);
    p1_k<<<N_GRAPHS * 4, 256>>>(h2, csr, roff, nb, P1);
    pool2_k<<<N_GRAPHS, 256>>>(h2, nb, P2);
    finale_k<<<N_GRAPHS, 64>>>(P1, P2, nb, Wrel3, brel3, Wroot3, Wlin, blin, out);
}

// round 4
// speedup vs baseline: 1.3709x; 1.0799x over previous
#include <cuda_runtime.h>
#include <cuda_bf16.h>
#include <cstdint>

#define N_NODES 50000
#define N_EDGES 1250000
#define N_GRAPHS 128
#define DH 64
#define DOUT 16

// -------- static device scratch --------
__device__ float g_h1[(size_t)N_NODES * DH];
__device__ float g_h2[(size_t)N_NODES * DH];
__device__ int   g_deg[N_NODES];
__device__ int   g_roff[N_NODES + 1];
__device__ int   g_cur[N_NODES];
__device__ int   g_csr[N_EDGES];
__device__ float g_P1[N_GRAPHS * DH];
__device__ float g_P2[N_GRAPHS * DH];
__device__ int   g_nb[N_GRAPHS + 1];

// ---------------- CSR build: histogram + (fused) graph bounds ----------------
__global__ void hist_bounds_k(const int* __restrict__ ei, int ne,
                              int* __restrict__ deg,
                              const int* __restrict__ batch,
                              int* __restrict__ nb) {
    int t = blockIdx.x * blockDim.x + threadIdx.x;
    if (t < ne) atomicAdd(&deg[__ldg(&ei[ne + t])], 1);
    if (t < N_NODES) {
        int b = __ldg(&batch[t]);
        if (t == 0) {
            for (int g = 0; g <= b; ++g) nb[g] = 0;
        } else {
            int p = __ldg(&batch[t - 1]);
            for (int g = p + 1; g <= b; ++g) nb[g] = t;
        }
        if (t == N_NODES - 1) {
            for (int g = b + 1; g <= N_GRAPHS; ++g) nb[g] = N_NODES;
        }
    }
}

__global__ void scan_k(const int* __restrict__ deg,
                       int* __restrict__ roff,
                       int* __restrict__ cur) {
    __shared__ int ssum[1024];
    const int PER = (N_NODES + 1023) / 1024;
    int t = threadIdx.x;
    int base = t * PER;
    int s = 0;
    for (int i = 0; i < PER; ++i) {
        int idx = base + i;
        if (idx < N_NODES) s += deg[idx];
    }
    ssum[t] = s;
    __syncthreads();
    for (int off = 1; off < 1024; off <<= 1) {
        int v = (t >= off) ? ssum[t - off] : 0;
        __syncthreads();
        ssum[t] += v;
        __syncthreads();
    }
    int run = ssum[t] - s;
    for (int i = 0; i < PER; ++i) {
        int idx = base + i;
        if (idx < N_NODES) {
            roff[idx] = run;
            cur[idx] = run;
            run += deg[idx];
        }
    }
    if (t == 1023) roff[N_NODES] = ssum[1023];
}

__global__ void fill_k(const int* __restrict__ ei, int ne,
                       int* __restrict__ cur, int* __restrict__ csr) {
    int t = blockIdx.x * blockDim.x + threadIdx.x;
    if (t < ne) {
        int d = __ldg(&ei[ne + t]);
        int p = atomicAdd(&cur[d], 1);
        csr[p] = __ldg(&ei[t]);
    }
}

// ------- fused layer: CSR gather (pipelined) + dual GEMM + bias + ReLU -------
#define LAYER_SMEM ((2 * 64 * 68 + 64 * 64) * 4)

__global__ __launch_bounds__(256, 4)
void layer_k(const float* __restrict__ X,
             const int* __restrict__ csr,
             const int* __restrict__ roff,
             const float* __restrict__ Wrel,
             const float* __restrict__ brel,
             const float* __restrict__ Wroot,
             float* __restrict__ out,
             int do_relu) {
    extern __shared__ float sm[];
    float (*sA)[68] = (float(*)[68])sm;
    float (*sX)[68] = (float(*)[68])(sm + 64 * 68);
    float (*sW)[64] = (float(*)[64])(sm + 2 * 64 * 68);
    __shared__ int sRow;

    const unsigned FULL = 0xffffffffu;
    int tid = threadIdx.x;
    int rowBase = blockIdx.x * 64;
    if (tid == 0) sRow = 0;

    for (int i = tid; i < 1024; i += 256)
        ((float4*)sW)[i] = ((const float4*)Wrel)[i];
    for (int i = tid; i < 1024; i += 256) {
        int r = i >> 4, c4 = i & 15;
        int g = rowBase + r;
        float4 v = (g < N_NODES) ? ((const float4*)(X + (size_t)g * DH))[c4]
                                 : make_float4(0.f, 0.f, 0.f, 0.f);
        *(float4*)&sX[r][c4 * 4] = v;
    }
    __syncthreads();

    // gather phase: dynamic row queue; idx prefetch pipeline, 8 rows in flight
    int lane = tid & 31;
    const float2* X2 = (const float2*)X;
    for (;;) {
        int r = 0;
        if (lane == 0) r = atomicAdd(&sRow, 1);
        r = __shfl_sync(FULL, r, 0);
        if (r >= 64) break;
        int g = rowBase + r;
        float2 acc = make_float2(0.f, 0.f);
        if (g < N_NODES) {
            int j = __ldg(&roff[g]);
            int end = __ldg(&roff[g + 1]);
            // prefetch first index batch
            int nxt = 0;
            if (lane < 8 && j + lane < end) nxt = __ldg(&csr[j + lane]);
            while (j + 8 <= end) {
                int curIdx = nxt;
                int jn = j + 8;
                // prefetch next batch while row loads are in flight
                nxt = (lane < 8 && jn + lane < end) ? __ldg(&csr[jn + lane]) : 0;
                int s0 = __shfl_sync(FULL, curIdx, 0);
                int s1 = __shfl_sync(FULL, curIdx, 1);
                int s2 = __shfl_sync(FULL, curIdx, 2);
                int s3 = __shfl_sync(FULL, curIdx, 3);
                int s4 = __shfl_sync(FULL, curIdx, 4);
                int s5 = __shfl_sync(FULL, curIdx, 5);
                int s6 = __shfl_sync(FULL, curIdx, 6);
                int s7 = __shfl_sync(FULL, curIdx, 7);
                float2 v0 = __ldg(&X2[(size_t)s0 * 32 + lane]);
                float2 v1 = __ldg(&X2[(size_t)s1 * 32 + lane]);
                float2 v2 = __ldg(&X2[(size_t)s2 * 32 + lane]);
                float2 v3 = __ldg(&X2[(size_t)s3 * 32 + lane]);
                float2 v4 = __ldg(&X2[(size_t)s4 * 32 + lane]);
                float2 v5 = __ldg(&X2[(size_t)s5 * 32 + lane]);
                float2 v6 = __ldg(&X2[(size_t)s6 * 32 + lane]);
                float2 v7 = __ldg(&X2[(size_t)s7 * 32 + lane]);
                acc.x += v0.x + v1.x + v2.x + v3.x + v4.x + v5.x + v6.x + v7.x;
                acc.y += v0.y + v1.y + v2.y + v3.y + v4.y + v5.y + v6.y + v7.y;
                j = jn;
            }
            // tail: indices already in nxt lanes 0..(end-j-1)
            int rem = end - j;
            for (int t = 0; t < rem; ++t) {
                int s = __shfl_sync(FULL, nxt, t);
                float2 v = __ldg(&X2[(size_t)s * 32 + lane]);
                acc.x += v.x; acc.y += v.y;
            }
        }
        sA[r][lane * 2] = acc.x;
        sA[r][lane * 2 + 1] = acc.y;
    }
    __syncthreads();

    int tx = tid & 15, ty = tid >> 4;
    float acc[4][4] = {};

    #pragma unroll 16
    for (int k = 0; k < 64; ++k) {
        float4 bv = *(const float4*)&sW[k][tx * 4];
        float a0 = sA[ty * 4 + 0][k];
        float a1 = sA[ty * 4 + 1][k];
        float a2 = sA[ty * 4 + 2][k];
        float a3 = sA[ty * 4 + 3][k];
        acc[0][0] += a0 * bv.x; acc[0][1] += a0 * bv.y; acc[0][2] += a0 * bv.z; acc[0][3] += a0 * bv.w;
        acc[1][0] += a1 * bv.x; acc[1][1] += a1 * bv.y; acc[1][2] += a1 * bv.z; acc[1][3] += a1 * bv.w;
        acc[2][0] += a2 * bv.x; acc[2][1] += a2 * bv.y; acc[2][2] += a2 * bv.z; acc[2][3] += a2 * bv.w;
        acc[3][0] += a3 * bv.x; acc[3][1] += a3 * bv.y; acc[3][2] += a3 * bv.z; acc[3][3] += a3 * bv.w;
    }
    __syncthreads();

    for (int i = tid; i < 1024; i += 256)
        ((float4*)sW)[i] = ((const float4*)Wroot)[i];
    __syncthreads();

    #pragma unroll 16
    for (int k = 0; k < 64; ++k) {
        float4 bv = *(const float4*)&sW[k][tx * 4];
        float a0 = sX[ty * 4 + 0][k];
        float a1 = sX[ty * 4 + 1][k];
        float a2 = sX[ty * 4 + 2][k];
        float a3 = sX[ty * 4 + 3][k];
        acc[0][0] += a0 * bv.x; acc[0][1] += a0 * bv.y; acc[0][2] += a0 * bv.z; acc[0][3] += a0 * bv.w;
        acc[1][0] += a1 * bv.x; acc[1][1] += a1 * bv.y; acc[1][2] += a1 * bv.z; acc[1][3] += a1 * bv.w;
        acc[2][0] += a2 * bv.x; acc[2][1] += a2 * bv.y; acc[2][2] += a2 * bv.z; acc[2][3] += a2 * bv.w;
        acc[3][0] += a3 * bv.x; acc[3][1] += a3 * bv.y; acc[3][2] += a3 * bv.z; acc[3][3] += a3 * bv.w;
    }

    float4 bb = *(const float4*)&brel[tx * 4];
    #pragma unroll
    for (int i = 0; i < 4; ++i) {
        int g = rowBase + ty * 4 + i;
        if (g < N_NODES) {
            float4 o;
            o.x = acc[i][0] + bb.x;
            o.y = acc[i][1] + bb.y;
            o.z = acc[i][2] + bb.z;
            o.w = acc[i][3] + bb.w;
            if (do_relu) {
                o.x = fmaxf(o.x, 0.f); o.y = fmaxf(o.y, 0.f);
                o.z = fmaxf(o.z, 0.f); o.w = fmaxf(o.w, 0.f);
            }
            *(float4*)(out + (size_t)g * DH + tx * 4) = o;
        }
    }
}

// ---- P1[g] = sum over edges of graph g of h2[src] ----
__global__ void p1_k(const float* __restrict__ H,
                     const int* __restrict__ csr,
                     const int* __restrict__ roff,
                     const int* __restrict__ nb,
                     float* __restrict__ P1) {
    int g = blockIdx.x >> 2, part = blockIdx.x & 3;
    int ns = __ldg(&nb[g]), neE = __ldg(&nb[g + 1]);
    int es = __ldg(&roff[ns]), ee = __ldg(&roff[neE]);
    long long len = ee - es;
    int start = es + (int)((len * part) >> 2);
    int end = es + (int)((len * (part + 1)) >> 2);
    int grp = threadIdx.x >> 4, lane = threadIdx.x & 15;
    const float4* H4 = (const float4*)H;
    float4 acc = make_float4(0.f, 0.f, 0.f, 0.f);
    int j = start + grp;
    for (; j + 48 < end; j += 64) {
        int s0 = __ldg(&csr[j]);
        int s1 = __ldg(&csr[j + 16]);
        int s2 = __ldg(&csr[j + 32]);
        int s3 = __ldg(&csr[j + 48]);
        float4 v0 = __ldg(&H4[(size_t)s0 * 16 + lane]);
        float4 v1 = __ldg(&H4[(size_t)s1 * 16 + lane]);
        float4 v2 = __ldg(&H4[(size_t)s2 * 16 + lane]);
        float4 v3 = __ldg(&H4[(size_t)s3 * 16 + lane]);
        acc.x += v0.x + v1.x + v2.x + v3.x;
        acc.y += v0.y + v1.y + v2.y + v3.y;
        acc.z += v0.z + v1.z + v2.z + v3.z;
        acc.w += v0.w + v1.w + v2.w + v3.w;
    }
    for (; j < end; j += 16) {
        int s0 = __ldg(&csr[j]);
        float4 v0 = __ldg(&H4[(size_t)s0 * 16 + lane]);
        acc.x += v0.x; acc.y += v0.y; acc.z += v0.z; acc.w += v0.w;
    }
    __shared__ float sRed[16][68];
    *(float4*)&sRed[grp][lane * 4] = acc;
    __syncthreads();
    if (threadIdx.x < 16) {
        int q = threadIdx.x;
        float4 s = make_float4(0.f, 0.f, 0.f, 0.f);
        #pragma unroll
        for (int t = 0; t < 16; ++t) {
            float4 v = *(float4*)&sRed[t][q * 4];
            s.x += v.x; s.y += v.y; s.z += v.z; s.w += v.w;
        }
        float* dst = P1 + g * DH + q * 4;
        asm volatile("red.global.add.v4.f32 [%0], {%1,%2,%3,%4};"
                     :: "l"(dst), "f"(s.x), "f"(s.y), "f"(s.z), "f"(s.w)
                     : "memory");
    }
}

// ---- P2[g] = sum over nodes of graph g of h2 ----
__global__ void pool2_k(const float* __restrict__ H,
                        const int* __restrict__ nb,
                        float* __restrict__ P2) {
    int g = blockIdx.x;
    int s = __ldg(&nb[g]), e = __ldg(&nb[g + 1]);
    int grp = threadIdx.x >> 4, lane = threadIdx.x & 15;
    const float4* H4 = (const float4*)H;
    float4 acc = make_float4(0.f, 0.f, 0.f, 0.f);
    for (int r = s + grp; r < e; r += 16) {
        float4 v = __ldg(&H4[(size_t)r * 16 + lane]);
        acc.x += v.x; acc.y += v.y; acc.z += v.z; acc.w += v.w;
    }
    __shared__ float sRed[16][68];
    *(float4*)&sRed[grp][lane * 4] = acc;
    __syncthreads();
    if (threadIdx.x < 16) {
        int q = threadIdx.x;
        float4 sv = make_float4(0.f, 0.f, 0.f, 0.f);
        #pragma unroll
        for (int t = 0; t < 16; ++t) {
            float4 v = *(float4*)&sRed[t][q * 4];
            sv.x += v.x; sv.y += v.y; sv.z += v.z; sv.w += v.w;
        }
        *(float4*)&P2[g * DH + q * 4] = sv;
    }
}

// ---- finale ----
__global__ void finale_k(const float* __restrict__ P1,
                         const float* __restrict__ P2,
                         const int* __restrict__ nb,
                         const float* __restrict__ Wrel,
                         const float* __restrict__ brel,
                         const float* __restrict__ Wroot,
                         const float* __restrict__ Wlin,
                         const float* __restrict__ blin,
                         float* __restrict__ out) {
    int g = blockIdx.x;
    int c = threadIdx.x;
    __shared__ float st[64];
    float cnt = fmaxf((float)(nb[g + 1] - nb[g]), 1.0f);
    float t = 0.f;
    #pragma unroll 8
    for (int k = 0; k < 64; ++k)
        t += P1[g * DH + k] * Wrel[k * DH + c] + P2[g * DH + k] * Wroot[k * DH + c];
    st[c] = t / cnt + brel[c];
    __syncthreads();
    if (c < DOUT) {
        float o = blin[c];
        #pragma unroll 8
        for (int k = 0; k < 64; ++k)
            o += st[k] * Wlin[k * DOUT + c];
        out[g * DOUT + c] = o;
    }
}

extern "C" void kernel_launch(void* const* d_in, const int* in_sizes, int n_in,
                              void* d_out, int out_size) {
    const float* x      = (const float*)d_in[0];
    const int*   ei     = (const int*)d_in[1];
    const int*   batch  = (const int*)d_in[3];
    const float* Wrel1  = (const float*)d_in[4];
    const float* brel1  = (const float*)d_in[5];
    const float* Wroot1 = (const float*)d_in[6];
    const float* Wrel2  = (const float*)d_in[7];
    const float* brel2  = (const float*)d_in[8];
    const float* Wroot2 = (const float*)d_in[9];
    const float* Wrel3  = (const float*)d_in[10];
    const float* brel3  = (const float*)d_in[11];
    const float* Wroot3 = (const float*)d_in[12];
    const float* Wlin   = (const float*)d_in[13];
    const float* blin   = (const float*)d_in[14];
    float* out = (float*)d_out;

    int ne = in_sizes[1] / 2;

    void *h1_p, *h2_p, *deg_p, *roff_p, *cur_p, *csr_p, *p1_p, *p2_p, *nb_p;
    cudaGetSymbolAddress(&h1_p, g_h1);
    cudaGetSymbolAddress(&h2_p, g_h2);
    cudaGetSymbolAddress(&deg_p, g_deg);
    cudaGetSymbolAddress(&roff_p, g_roff);
    cudaGetSymbolAddress(&cur_p, g_cur);
    cudaGetSymbolAddress(&csr_p, g_csr);
    cudaGetSymbolAddress(&p1_p, g_P1);
    cudaGetSymbolAddress(&p2_p, g_P2);
    cudaGetSymbolAddress(&nb_p, g_nb);

    float* h1 = (float*)h1_p;
    float* h2 = (float*)h2_p;
    int* deg = (int*)deg_p;
    int* roff = (int*)roff_p;
    int* cur = (int*)cur_p;
    int* csr = (int*)csr_p;
    float* P1 = (float*)p1_p;
    float* P2 = (float*)p2_p;
    int* nb = (int*)nb_p;

    static int attr_set = 0;
    if (!attr_set) {
        cudaFuncSetAttribute(layer_k,
                             cudaFuncAttributeMaxDynamicSharedMemorySize, LAYER_SMEM);
        attr_set = 1;
    }

    int edgeBlocks = (ne + 255) / 256;
    int gemmBlocks = (N_NODES + 63) / 64;

    // memsets first (also keeps kernel launch indices stable for profiling)
    cudaMemsetAsync(deg, 0, N_NODES * sizeof(int), 0);
    cudaMemsetAsync(P1, 0, N_GRAPHS * DH * sizeof(float), 0);

    // CSR build (+ fused graph boundaries)
    hist_bounds_k<<<edgeBlocks, 256>>>(ei, ne, deg, batch, nb);
    scan_k<<<1, 1024>>>(deg, roff, cur);
    fill_k<<<edgeBlocks, 256>>>(ei, ne, cur, csr);

    // layers 1-2 (fused gather + GEMM)
    layer_k<<<gemmBlocks, 256, LAYER_SMEM>>>(x,  csr, roff, Wrel1, brel1, Wroot1, h1, 1);
    layer_k<<<gemmBlocks, 256, LAYER_SMEM>>>(h1, csr, roff, Wrel2, brel2, Wroot2, h2, 1);

    // layer 3 folded into pooled space
    p1_k<<<N_GRAPHS * 4, 256>>>(h2, csr, roff, nb, P1);
    pool2_k<<<N_GRAPHS, 256>>>(h2, nb, P2);
    finale_k<<<N_GRAPHS, 64>>>(P1, P2, nb, Wrel3, brel3, Wroot3, Wlin, blin, out);
}

// round 5
// speedup vs baseline: 1.9516x; 1.4236x over previous
#include <cuda_runtime.h>
#include <cuda_bf16.h>
#include <cstdint>

#define N_NODES 50000
#define N_EDGES 1250000
#define N_GRAPHS 128
#define DH 64
#define DOUT 16
#define SCAN_BLOCKS ((N_NODES + 1023) / 1024)   // 49

// -------- static device scratch --------
__device__ float g_h1[(size_t)N_NODES * DH];
__device__ float g_h2[(size_t)N_NODES * DH];
__device__ int   g_deg[N_NODES];
__device__ int   g_roff[N_NODES + 1];
__device__ int   g_cur[N_NODES];
__device__ int   g_csr[N_EDGES + 8];     // +8 pad: index prefetch may run past end
__device__ float g_P1[N_GRAPHS * DH];
__device__ float g_P2[N_GRAPHS * DH];
__device__ int   g_nb[N_GRAPHS + 1];
__device__ int   g_bsum[SCAN_BLOCKS];
__device__ int   g_boff[SCAN_BLOCKS];

// ---------------- CSR build: histogram + (fused) graph bounds ----------------
__global__ void hist_bounds_k(const int* __restrict__ ei, int ne,
                              int* __restrict__ deg,
                              const int* __restrict__ batch,
                              int* __restrict__ nb) {
    int t = blockIdx.x * blockDim.x + threadIdx.x;
    if (t < ne) atomicAdd(&deg[__ldg(&ei[ne + t])], 1);
    if (t < N_NODES) {
        int b = __ldg(&batch[t]);
        if (t == 0) {
            for (int g = 0; g <= b; ++g) nb[g] = 0;
        } else {
            int p = __ldg(&batch[t - 1]);
            for (int g = p + 1; g <= b; ++g) nb[g] = t;
        }
        if (t == N_NODES - 1) {
            for (int g = b + 1; g <= N_GRAPHS; ++g) nb[g] = N_NODES;
        }
    }
}

// ---- coalesced 3-phase scan of deg -> roff/cur ----
__global__ void s1_k(const int* __restrict__ deg, int* __restrict__ bsum) {
    __shared__ int red[1024];
    int n = blockIdx.x * 1024 + threadIdx.x;
    red[threadIdx.x] = (n < N_NODES) ? __ldg(&deg[n]) : 0;
    __syncthreads();
    #pragma unroll
    for (int s = 512; s > 0; s >>= 1) {
        if (threadIdx.x < s) red[threadIdx.x] += red[threadIdx.x + s];
        __syncthreads();
    }
    if (threadIdx.x == 0) bsum[blockIdx.x] = red[0];
}

__global__ void s2_k(const int* __restrict__ bsum,
                     int* __restrict__ boff,
                     int* __restrict__ roff) {
    __shared__ int sv[64];
    int t = threadIdx.x;
    int v = (t < SCAN_BLOCKS) ? bsum[t] : 0;
    sv[t] = v;
    __syncthreads();
    #pragma unroll
    for (int o = 1; o < 64; o <<= 1) {
        int u = (t >= o) ? sv[t - o] : 0;
        __syncthreads();
        sv[t] += u;
        __syncthreads();
    }
    if (t < SCAN_BLOCKS) boff[t] = sv[t] - v;
    if (t == SCAN_BLOCKS - 1) roff[N_NODES] = sv[t];
}

__global__ void s3_k(const int* __restrict__ deg,
                     const int* __restrict__ boff,
                     int* __restrict__ roff,
                     int* __restrict__ cur) {
    __shared__ int sv[1024];
    int t = threadIdx.x;
    int n = blockIdx.x * 1024 + t;
    int v = (n < N_NODES) ? __ldg(&deg[n]) : 0;
    sv[t] = v;
    __syncthreads();
    #pragma unroll
    for (int o = 1; o < 1024; o <<= 1) {
        int u = (t >= o) ? sv[t - o] : 0;
        __syncthreads();
        sv[t] += u;
        __syncthreads();
    }
    if (n < N_NODES) {
        int ex = boff[blockIdx.x] + sv[t] - v;
        roff[n] = ex;
        cur[n] = ex;
    }
}

__global__ void fill_k(const int* __restrict__ ei, int ne,
                       int* __restrict__ cur, int* __restrict__ csr) {
    int t = blockIdx.x * blockDim.x + threadIdx.x;
    if (t < ne) {
        int d = __ldg(&ei[ne + t]);
        int p = atomicAdd(&cur[d], 1);
        csr[p] = __ldg(&ei[t]);
    }
}

// ------- fused layer: CSR gather (paired float4, streaming prefetch) + dual GEMM -------
#define LAYER_SMEM ((2 * 64 * 68 + 64 * 64) * 4)

__global__ __launch_bounds__(256, 4)
void layer_k(const float* __restrict__ X,
             const int* __restrict__ csr,
             const int* __restrict__ roff,
             const float* __restrict__ Wrel,
             const float* __restrict__ brel,
             const float* __restrict__ Wroot,
             float* __restrict__ out,
             int do_relu) {
    extern __shared__ float sm[];
    float (*sA)[68] = (float(*)[68])sm;
    float (*sX)[68] = (float(*)[68])(sm + 64 * 68);
    float (*sW)[64] = (float(*)[64])(sm + 2 * 64 * 68);

    const unsigned FULL = 0xffffffffu;
    int tid = threadIdx.x;
    int rowBase = blockIdx.x * 64;
    int warp = tid >> 5, lane = tid & 31;

    for (int i = tid; i < 1024; i += 256)
        ((float4*)sW)[i] = ((const float4*)Wrel)[i];
    for (int i = tid; i < 1024; i += 256) {
        int r = i >> 4, c4 = i & 15;
        int g = rowBase + r;
        float4 v = (g < N_NODES) ? ((const float4*)(X + (size_t)g * DH))[c4]
                                 : make_float4(0.f, 0.f, 0.f, 0.f);
        *(float4*)&sX[r][c4 * 4] = v;
    }

    // ---- gather: static 8 rows/warp (contiguous csr range), paired float4 ----
    const float4* X4 = (const float4*)X;
    int h = lane >> 4;      // half id: edge parity within a quad-batch
    int c = lane & 15;      // column group: 4 floats
    int rbase = rowBase + warp * 8;

    int off = 0;
    if (lane < 9) {
        int idx = rbase + lane;
        if (idx > N_NODES) idx = N_NODES;
        off = __ldg(&roff[idx]);
    }

    int j = __shfl_sync(FULL, off, 0);
    int nxt = (lane < 8) ? __ldg(&csr[j + lane]) : 0;

    #pragma unroll 1
    for (int rr = 0; rr < 8; ++rr) {
        int end = __shfl_sync(FULL, off, rr + 1);
        float4 acc = make_float4(0.f, 0.f, 0.f, 0.f);

        #pragma unroll 1
        while (j + 8 <= end) {
            int curI = nxt;
            nxt = (lane < 8) ? __ldg(&csr[j + 8 + lane]) : 0;  // streams across rows
            int s0 = __shfl_sync(FULL, curI, h * 4 + 0);
            int s1 = __shfl_sync(FULL, curI, h * 4 + 1);
            int s2 = __shfl_sync(FULL, curI, h * 4 + 2);
            int s3 = __shfl_sync(FULL, curI, h * 4 + 3);
            float4 v0 = __ldg(&X4[(size_t)s0 * 16 + c]);
            float4 v1 = __ldg(&X4[(size_t)s1 * 16 + c]);
            float4 v2 = __ldg(&X4[(size_t)s2 * 16 + c]);
            float4 v3 = __ldg(&X4[(size_t)s3 * 16 + c]);
            acc.x += v0.x + v1.x + v2.x + v3.x;
            acc.y += v0.y + v1.y + v2.y + v3.y;
            acc.z += v0.z + v1.z + v2.z + v3.z;
            acc.w += v0.w + v1.w + v2.w + v3.w;
            j += 8;
        }
        int rem = end - j;   // 0..7
        if (rem > 0) {
            int curI = nxt;  // lanes 0..rem-1 hold this row's tail indices
            #pragma unroll
            for (int t = 0; t < 7; t += 2) {
                if (t >= rem) break;
                int e = t + h;
                bool valid = e < rem;
                int s = __shfl_sync(FULL, curI, valid ? e : 0);
                float4 v = __ldg(&X4[(size_t)s * 16 + c]);
                if (valid) {
                    acc.x += v.x; acc.y += v.y; acc.z += v.z; acc.w += v.w;
                }
            }
            j = end;
            nxt = (lane < 8) ? __ldg(&csr[j + lane]) : 0;
        }
        // combine the two edge-halves
        acc.x += __shfl_xor_sync(FULL, acc.x, 16);
        acc.y += __shfl_xor_sync(FULL, acc.y, 16);
        acc.z += __shfl_xor_sync(FULL, acc.z, 16);
        acc.w += __shfl_xor_sync(FULL, acc.w, 16);
        if (lane < 16)
            *(float4*)&sA[warp * 8 + rr][c * 4] = acc;
    }
    __syncthreads();

    int tx = tid & 15, ty = tid >> 4;
    float acc[4][4] = {};

    #pragma unroll 16
    for (int k = 0; k < 64; ++k) {
        float4 bv = *(const float4*)&sW[k][tx * 4];
        float a0 = sA[ty * 4 + 0][k];
        float a1 = sA[ty * 4 + 1][k];
        float a2 = sA[ty * 4 + 2][k];
        float a3 = sA[ty * 4 + 3][k];
        acc[0][0] += a0 * bv.x; acc[0][1] += a0 * bv.y; acc[0][2] += a0 * bv.z; acc[0][3] += a0 * bv.w;
        acc[1][0] += a1 * bv.x; acc[1][1] += a1 * bv.y; acc[1][2] += a1 * bv.z; acc[1][3] += a1 * bv.w;
        acc[2][0] += a2 * bv.x; acc[2][1] += a2 * bv.y; acc[2][2] += a2 * bv.z; acc[2][3] += a2 * bv.w;
        acc[3][0] += a3 * bv.x; acc[3][1] += a3 * bv.y; acc[3][2] += a3 * bv.z; acc[3][3] += a3 * bv.w;
    }
    __syncthreads();

    for (int i = tid; i < 1024; i += 256)
        ((float4*)sW)[i] = ((const float4*)Wroot)[i];
    __syncthreads();

    #pragma unroll 16
    for (int k = 0; k < 64; ++k) {
        float4 bv = *(const float4*)&sW[k][tx * 4];
        float a0 = sX[ty * 4 + 0][k];
        float a1 = sX[ty * 4 + 1][k];
        float a2 = sX[ty * 4 + 2][k];
        float a3 = sX[ty * 4 + 3][k];
        acc[0][0] += a0 * bv.x; acc[0][1] += a0 * bv.y; acc[0][2] += a0 * bv.z; acc[0][3] += a0 * bv.w;
        acc[1][0] += a1 * bv.x; acc[1][1] += a1 * bv.y; acc[1][2] += a1 * bv.z; acc[1][3] += a1 * bv.w;
        acc[2][0] += a2 * bv.x; acc[2][1] += a2 * bv.y; acc[2][2] += a2 * bv.z; acc[2][3] += a2 * bv.w;
        acc[3][0] += a3 * bv.x; acc[3][1] += a3 * bv.y; acc[3][2] += a3 * bv.z; acc[3][3] += a3 * bv.w;
    }

    float4 bb = *(const float4*)&brel[tx * 4];
    #pragma unroll
    for (int i = 0; i < 4; ++i) {
        int g = rowBase + ty * 4 + i;
        if (g < N_NODES) {
            float4 o;
            o.x = acc[i][0] + bb.x;
            o.y = acc[i][1] + bb.y;
            o.z = acc[i][2] + bb.z;
            o.w = acc[i][3] + bb.w;
            if (do_relu) {
                o.x = fmaxf(o.x, 0.f); o.y = fmaxf(o.y, 0.f);
                o.z = fmaxf(o.z, 0.f); o.w = fmaxf(o.w, 0.f);
            }
            *(float4*)(out + (size_t)g * DH + tx * 4) = o;
        }
    }
}

// ---- P1[g] = sum over edges of graph g of h2[src] ----
__global__ void p1_k(const float* __restrict__ H,
                     const int* __restrict__ csr,
                     const int* __restrict__ roff,
                     const int* __restrict__ nb,
                     float* __restrict__ P1) {
    int g = blockIdx.x >> 2, part = blockIdx.x & 3;
    int ns = __ldg(&nb[g]), neE = __ldg(&nb[g + 1]);
    int es = __ldg(&roff[ns]), ee = __ldg(&roff[neE]);
    long long len = ee - es;
    int start = es + (int)((len * part) >> 2);
    int end = es + (int)((len * (part + 1)) >> 2);
    int grp = threadIdx.x >> 4, lane = threadIdx.x & 15;
    const float4* H4 = (const float4*)H;
    float4 acc = make_float4(0.f, 0.f, 0.f, 0.f);
    int j = start + grp;
    for (; j + 48 < end; j += 64) {
        int s0 = __ldg(&csr[j]);
        int s1 = __ldg(&csr[j + 16]);
        int s2 = __ldg(&csr[j + 32]);
        int s3 = __ldg(&csr[j + 48]);
        float4 v0 = __ldg(&H4[(size_t)s0 * 16 + lane]);
        float4 v1 = __ldg(&H4[(size_t)s1 * 16 + lane]);
        float4 v2 = __ldg(&H4[(size_t)s2 * 16 + lane]);
        float4 v3 = __ldg(&H4[(size_t)s3 * 16 + lane]);
        acc.x += v0.x + v1.x + v2.x + v3.x;
        acc.y += v0.y + v1.y + v2.y + v3.y;
        acc.z += v0.z + v1.z + v2.z + v3.z;
        acc.w += v0.w + v1.w + v2.w + v3.w;
    }
    for (; j < end; j += 16) {
        int s0 = __ldg(&csr[j]);
        float4 v0 = __ldg(&H4[(size_t)s0 * 16 + lane]);
        acc.x += v0.x; acc.y += v0.y; acc.z += v0.z; acc.w += v0.w;
    }
    __shared__ float sRed[16][68];
    *(float4*)&sRed[grp][lane * 4] = acc;
    __syncthreads();
    if (threadIdx.x < 16) {
        int q = threadIdx.x;
        float4 s = make_float4(0.f, 0.f, 0.f, 0.f);
        #pragma unroll
        for (int t = 0; t < 16; ++t) {
            float4 v = *(float4*)&sRed[t][q * 4];
            s.x += v.x; s.y += v.y; s.z += v.z; s.w += v.w;
        }
        float* dst = P1 + g * DH + q * 4;
        asm volatile("red.global.add.v4.f32 [%0], {%1,%2,%3,%4};"
                     :: "l"(dst), "f"(s.x), "f"(s.y), "f"(s.z), "f"(s.w)
                     : "memory");
    }
}

// ---- P2[g] = sum over nodes of graph g of h2 ----
__global__ void pool2_k(const float* __restrict__ H,
                        const int* __restrict__ nb,
                        float* __restrict__ P2) {
    int g = blockIdx.x;
    int s = __ldg(&nb[g]), e = __ldg(&nb[g + 1]);
    int grp = threadIdx.x >> 4, lane = threadIdx.x & 15;
    const float4* H4 = (const float4*)H;
    float4 acc = make_float4(0.f, 0.f, 0.f, 0.f);
    for (int r = s + grp; r < e; r += 16) {
        float4 v = __ldg(&H4[(size_t)r * 16 + lane]);
        acc.x += v.x; acc.y += v.y; acc.z += v.z; acc.w += v.w;
    }
    __shared__ float sRed[16][68];
    *(float4*)&sRed[grp][lane * 4] = acc;
    __syncthreads();
    if (threadIdx.x < 16) {
        int q = threadIdx.x;
        float4 sv = make_float4(0.f, 0.f, 0.f, 0.f);
        #pragma unroll
        for (int t = 0; t < 16; ++t) {
            float4 v = *(float4*)&sRed[t][q * 4];
            sv.x += v.x; sv.y += v.y; sv.z += v.z; sv.w += v.w;
        }
        *(float4*)&P2[g * DH + q * 4] = sv;
    }
}

// ---- finale ----
__global__ void finale_k(const float* __restrict__ P1,
                         const float* __restrict__ P2,
                         const int* __restrict__ nb,
                         const float* __restrict__ Wrel,
                         const float* __restrict__ brel,
                         const float* __restrict__ Wroot,
                         const float* __restrict__ Wlin,
                         const float* __restrict__ blin,
                         float* __restrict__ out) {
    int g = blockIdx.x;
    int c = threadIdx.x;
    __shared__ float st[64];
    float cnt = fmaxf((float)(nb[g + 1] - nb[g]), 1.0f);
    float t = 0.f;
    #pragma unroll 8
    for (int k = 0; k < 64; ++k)
        t += P1[g * DH + k] * Wrel[k * DH + c] + P2[g * DH + k] * Wroot[k * DH + c];
    st[c] = t / cnt + brel[c];
    __syncthreads();
    if (c < DOUT) {
        float o = blin[c];
        #pragma unroll 8
        for (int k = 0; k < 64; ++k)
            o += st[k] * Wlin[k * DOUT + c];
        out[g * DOUT + c] = o;
    }
}

extern "C" void kernel_launch(void* const* d_in, const int* in_sizes, int n_in,
                              void* d_out, int out_size) {
    const float* x      = (const float*)d_in[0];
    const int*   ei     = (const int*)d_in[1];
    const int*   batch  = (const int*)d_in[3];
    const float* Wrel1  = (const float*)d_in[4];
    const float* brel1  = (const float*)d_in[5];
    const float* Wroot1 = (const float*)d_in[6];
    const float* Wrel2  = (const float*)d_in[7];
    const float* brel2  = (const float*)d_in[8];
    const float* Wroot2 = (const float*)d_in[9];
    const float* Wrel3  = (const float*)d_in[10];
    const float* brel3  = (const float*)d_in[11];
    const float* Wroot3 = (const float*)d_in[12];
    const float* Wlin   = (const float*)d_in[13];
    const float* blin   = (const float*)d_in[14];
    float* out = (float*)d_out;

    int ne = in_sizes[1] / 2;

    void *h1_p, *h2_p, *deg_p, *roff_p, *cur_p, *csr_p, *p1_p, *p2_p, *nb_p, *bs_p, *bo_p;
    cudaGetSymbolAddress(&h1_p, g_h1);
    cudaGetSymbolAddress(&h2_p, g_h2);
    cudaGetSymbolAddress(&deg_p, g_deg);
    cudaGetSymbolAddress(&roff_p, g_roff);
    cudaGetSymbolAddress(&cur_p, g_cur);
    cudaGetSymbolAddress(&csr_p, g_csr);
    cudaGetSymbolAddress(&p1_p, g_P1);
    cudaGetSymbolAddress(&p2_p, g_P2);
    cudaGetSymbolAddress(&nb_p, g_nb);
    cudaGetSymbolAddress(&bs_p, g_bsum);
    cudaGetSymbolAddress(&bo_p, g_boff);

    float* h1 = (float*)h1_p;
    float* h2 = (float*)h2_p;
    int* deg = (int*)deg_p;
    int* roff = (int*)roff_p;
    int* cur = (int*)cur_p;
    int* csr = (int*)csr_p;
    float* P1 = (float*)p1_p;
    float* P2 = (float*)p2_p;
    int* nb = (int*)nb_p;
    int* bsum = (int*)bs_p;
    int* boff = (int*)bo_p;

    static int attr_set = 0;
    if (!attr_set) {
        cudaFuncSetAttribute(layer_k,
                             cudaFuncAttributeMaxDynamicSharedMemorySize, LAYER_SMEM);
        attr_set = 1;
    }

    int edgeBlocks = (ne + 255) / 256;
    int gemmBlocks = (N_NODES + 63) / 64;

    cudaMemsetAsync(deg, 0, N_NODES * sizeof(int), 0);
    cudaMemsetAsync(P1, 0, N_GRAPHS * DH * sizeof(float), 0);

    // CSR build (+ fused graph boundaries), coalesced 3-phase scan
    hist_bounds_k<<<edgeBlocks, 256>>>(ei, ne, deg, batch, nb);
    s1_k<<<SCAN_BLOCKS, 1024>>>(deg, bsum);
    s2_k<<<1, 64>>>(bsum, boff, roff);
    s3_k<<<SCAN_BLOCKS, 1024>>>(deg, boff, roff, cur);
    fill_k<<<edgeBlocks, 256>>>(ei, ne, cur, csr);

    // layers 1-2 (fused gather + GEMM)
    layer_k<<<gemmBlocks, 256, LAYER_SMEM>>>(x,  csr, roff, Wrel1, brel1, Wroot1, h1, 1);
    layer_k<<<gemmBlocks, 256, LAYER_SMEM>>>(h1, csr, roff, Wrel2, brel2, Wroot2, h2, 1);

    // layer 3 folded into pooled space
    p1_k<<<N_GRAPHS * 4, 256>>>(h2, csr, roff, nb, P1);
    pool2_k<<<N_GRAPHS, 256>>>(h2, nb, P2);
    finale_k<<<N_GRAPHS, 64>>>(P1, P2, nb, Wrel3, brel3, Wroot3, Wlin, blin, out);
}

// round 6
// speedup vs baseline: 2.0456x; 1.0482x over previous
#include <cuda_runtime.h>
#include <cuda_bf16.h>
#include <cstdint>

#define N_NODES 50000
#define N_GRAPHS 128
#define DH 64
#define DOUT 16
#define SCAN_BLOCKS ((N_NODES + 1023) / 1024)   // 49
#define N_EDGES 1250000

// -------- static device scratch --------
__device__ float g_h1[(size_t)N_NODES * DH];
__device__ float g_h2[(size_t)N_NODES * DH];
__device__ uint4 g_xb[(size_t)N_NODES * 8];    // bf16 shadow of layer input (128B/row)
__device__ uint4 g_h1b[(size_t)N_NODES * 8];
__device__ uint4 g_h2b[(size_t)N_NODES * 8];
__device__ int   g_deg[N_NODES];
__device__ int   g_roff[N_NODES + 1];
__device__ int   g_cur[N_NODES];
__device__ int   g_csr[N_EDGES + 16];          // pad: index prefetch runs past end
__device__ float g_P1[N_GRAPHS * DH];
__device__ float g_P2[N_GRAPHS * DH];
__device__ int   g_nb[N_GRAPHS + 1];
__device__ int   g_bsum[SCAN_BLOCKS];

// unpack 8 bf16 (uint4) and accumulate into 8 fp32 (shift = exact bf16->f32)
#define ACC8(v)                                                         \
    do {                                                                \
        a0 += __uint_as_float((v).x << 16);                             \
        a1 += __uint_as_float((v).x & 0xffff0000u);                     \
        a2 += __uint_as_float((v).y << 16);                             \
        a3 += __uint_as_float((v).y & 0xffff0000u);                     \
        a4 += __uint_as_float((v).z << 16);                             \
        a5 += __uint_as_float((v).z & 0xffff0000u);                     \
        a6 += __uint_as_float((v).w << 16);                             \
        a7 += __uint_as_float((v).w & 0xffff0000u);                     \
    } while (0)

// ---------------- CSR build: histogram + graph bounds + x->bf16 convert ----------------
__global__ void hist_bounds_k(const int* __restrict__ ei, int ne,
                              int* __restrict__ deg,
                              const int* __restrict__ batch,
                              int* __restrict__ nb,
                              const float* __restrict__ x,
                              __nv_bfloat162* __restrict__ xb) {
    int t = blockIdx.x * blockDim.x + threadIdx.x;
    if (t < ne) atomicAdd(&deg[__ldg(&ei[ne + t])], 1);
    if (t < N_NODES) {
        int b = __ldg(&batch[t]);
        if (t == 0) {
            for (int g = 0; g <= b; ++g) nb[g] = 0;
        } else {
            int p = __ldg(&batch[t - 1]);
            for (int g = p + 1; g <= b; ++g) nb[g] = t;
        }
        if (t == N_NODES - 1) {
            for (int g = b + 1; g <= N_GRAPHS; ++g) nb[g] = N_NODES;
        }
    }
    // convert x to bf16 shadow (grid-stride over float2 pairs)
    const float2* x2 = (const float2*)x;
    int stride = gridDim.x * blockDim.x;
    for (int i = t; i < N_NODES * DH / 2; i += stride) {
        float2 v = __ldg(&x2[i]);
        xb[i] = __float22bfloat162_rn(v);
    }
}

// ---- coalesced scan, 2 phases ----
__global__ void s1_k(const int* __restrict__ deg, int* __restrict__ bsum) {
    __shared__ int red[1024];
    int n = blockIdx.x * 1024 + threadIdx.x;
    red[threadIdx.x] = (n < N_NODES) ? __ldg(&deg[n]) : 0;
    __syncthreads();
    #pragma unroll
    for (int s = 512; s > 0; s >>= 1) {
        if (threadIdx.x < s) red[threadIdx.x] += red[threadIdx.x + s];
        __syncthreads();
    }
    if (threadIdx.x == 0) bsum[blockIdx.x] = red[0];
}

__global__ void s3_k(const int* __restrict__ deg,
                     const int* __restrict__ bsum,
                     int* __restrict__ roff,
                     int* __restrict__ cur) {
    __shared__ int sv[1024];
    __shared__ int sb[64];
    __shared__ int bpref;
    int t = threadIdx.x;
    if (t < 64) sb[t] = (t < SCAN_BLOCKS && t < blockIdx.x) ? __ldg(&bsum[t]) : 0;
    __syncthreads();
    if (t < 32) {
        int v = sb[t] + sb[t + 32];
        #pragma unroll
        for (int o = 16; o > 0; o >>= 1)
            v += __shfl_down_sync(0xffffffffu, v, o);
        if (t == 0) bpref = v;
    }
    int n = blockIdx.x * 1024 + t;
    int dv = (n < N_NODES) ? __ldg(&deg[n]) : 0;
    sv[t] = dv;
    __syncthreads();
    #pragma unroll
    for (int o = 1; o < 1024; o <<= 1) {
        int u = (t >= o) ? sv[t - o] : 0;
        __syncthreads();
        sv[t] += u;
        __syncthreads();
    }
    int ex = bpref + sv[t] - dv;
    if (n < N_NODES) {
        roff[n] = ex;
        cur[n] = ex;
    }
    if (blockIdx.x == SCAN_BLOCKS - 1 && t == 1023)
        roff[N_NODES] = bpref + sv[1023];
}

__global__ void fill_k(const int* __restrict__ ei, int ne,
                       int* __restrict__ cur, int* __restrict__ csr) {
    int t = blockIdx.x * blockDim.x + threadIdx.x;
    if (t < ne) {
        int d = __ldg(&ei[ne + t]);
        int p = atomicAdd(&cur[d], 1);
        csr[p] = __ldg(&ei[t]);
    }
}

// ------- fused layer: bf16 CSR gather + fp32 dual GEMM + bias + ReLU -------
#define LAYER_SMEM ((2 * 64 * 68 + 64 * 64) * 4)

__global__ __launch_bounds__(256, 4)
void layer_k(const float* __restrict__ X,        // fp32 (root path)
             const uint4* __restrict__ Xb,       // bf16 shadow (gather path)
             const int* __restrict__ csr,
             const int* __restrict__ roff,
             const float* __restrict__ Wrel,
             const float* __restrict__ brel,
             const float* __restrict__ Wroot,
             float* __restrict__ out,
             uint4* __restrict__ outb,           // bf16 shadow of out (may be null)
             int do_relu) {
    extern __shared__ float sm[];
    float (*sA)[68] = (float(*)[68])sm;
    float (*sX)[68] = (float(*)[68])(sm + 64 * 68);
    float (*sW)[64] = (float(*)[64])(sm + 2 * 64 * 68);

    const unsigned FULL = 0xffffffffu;
    int tid = threadIdx.x;
    int rowBase = blockIdx.x * 64;
    int warp = tid >> 5, lane = tid & 31;

    for (int i = tid; i < 1024; i += 256)
        ((float4*)sW)[i] = ((const float4*)Wrel)[i];
    for (int i = tid; i < 1024; i += 256) {
        int r = i >> 4, c4 = i & 15;
        int g = rowBase + r;
        float4 v = (g < N_NODES) ? ((const float4*)(X + (size_t)g * DH))[c4]
                                 : make_float4(0.f, 0.f, 0.f, 0.f);
        *(float4*)&sX[r][c4 * 4] = v;
    }

    // ---- gather: 8 rows/warp, bf16 rows (128B), 4 edges per LDG.128, 16-edge batches ----
    int h = lane >> 3;      // edge slot within quad (0..3)
    int c = lane & 7;       // 16B column group (0..7)
    int rbase = rowBase + warp * 8;

    int off = 0;
    if (lane < 9) {
        int idx = rbase + lane;
        if (idx > N_NODES) idx = N_NODES;
        off = __ldg(&roff[idx]);
    }

    int j = __shfl_sync(FULL, off, 0);
    int nxt = (lane < 16) ? __ldg(&csr[j + lane]) : 0;

    #pragma unroll 1
    for (int rr = 0; rr < 8; ++rr) {
        int end = __shfl_sync(FULL, off, rr + 1);
        float a0 = 0.f, a1 = 0.f, a2 = 0.f, a3 = 0.f;
        float a4 = 0.f, a5 = 0.f, a6 = 0.f, a7 = 0.f;

        #pragma unroll 1
        while (j + 16 <= end) {
            int curI = nxt;
            nxt = (lane < 16) ? __ldg(&csr[j + 16 + lane]) : 0;
            int s0 = __shfl_sync(FULL, curI, 0 + h);
            int s1 = __shfl_sync(FULL, curI, 4 + h);
            int s2 = __shfl_sync(FULL, curI, 8 + h);
            int s3 = __shfl_sync(FULL, curI, 12 + h);
            uint4 v0 = __ldg(&Xb[(size_t)s0 * 8 + c]);
            uint4 v1 = __ldg(&Xb[(size_t)s1 * 8 + c]);
            uint4 v2 = __ldg(&Xb[(size_t)s2 * 8 + c]);
            uint4 v3 = __ldg(&Xb[(size_t)s3 * 8 + c]);
            ACC8(v0); ACC8(v1); ACC8(v2); ACC8(v3);
            j += 16;
        }
        int rem = end - j;   // 0..15
        if (rem > 0) {
            int curI = nxt;
            #pragma unroll
            for (int base = 0; base < 16; base += 4) {
                if (base >= rem) break;
                int e = base + h;
                bool valid = e < rem;
                int s = __shfl_sync(FULL, curI, valid ? e : 0);
                uint4 v = __ldg(&Xb[(size_t)s * 8 + c]);
                if (valid) { ACC8(v); }
            }
            j = end;
            nxt = (lane < 16) ? __ldg(&csr[j + lane]) : 0;
        }
        // reduce the 4 edge-slots (h groups)
        #pragma unroll
        for (int o = 8; o <= 16; o <<= 1) {
            a0 += __shfl_xor_sync(FULL, a0, o);
            a1 += __shfl_xor_sync(FULL, a1, o);
            a2 += __shfl_xor_sync(FULL, a2, o);
            a3 += __shfl_xor_sync(FULL, a3, o);
            a4 += __shfl_xor_sync(FULL, a4, o);
            a5 += __shfl_xor_sync(FULL, a5, o);
            a6 += __shfl_xor_sync(FULL, a6, o);
            a7 += __shfl_xor_sync(FULL, a7, o);
        }
        if (lane < 8) {
            int r = warp * 8 + rr;
            *(float4*)&sA[r][c * 8]     = make_float4(a0, a1, a2, a3);
            *(float4*)&sA[r][c * 8 + 4] = make_float4(a4, a5, a6, a7);
        }
    }
    __syncthreads();

    int tx = tid & 15, ty = tid >> 4;
    float acc[4][4] = {};

    #pragma unroll 16
    for (int k = 0; k < 64; ++k) {
        float4 bv = *(const float4*)&sW[k][tx * 4];
        float b0 = sA[ty * 4 + 0][k];
        float b1 = sA[ty * 4 + 1][k];
        float b2 = sA[ty * 4 + 2][k];
        float b3 = sA[ty * 4 + 3][k];
        acc[0][0] += b0 * bv.x; acc[0][1] += b0 * bv.y; acc[0][2] += b0 * bv.z; acc[0][3] += b0 * bv.w;
        acc[1][0] += b1 * bv.x; acc[1][1] += b1 * bv.y; acc[1][2] += b1 * bv.z; acc[1][3] += b1 * bv.w;
        acc[2][0] += b2 * bv.x; acc[2][1] += b2 * bv.y; acc[2][2] += b2 * bv.z; acc[2][3] += b2 * bv.w;
        acc[3][0] += b3 * bv.x; acc[3][1] += b3 * bv.y; acc[3][2] += b3 * bv.z; acc[3][3] += b3 * bv.w;
    }
    __syncthreads();

    for (int i = tid; i < 1024; i += 256)
        ((float4*)sW)[i] = ((const float4*)Wroot)[i];
    __syncthreads();

    #pragma unroll 16
    for (int k = 0; k < 64; ++k) {
        float4 bv = *(const float4*)&sW[k][tx * 4];
        float b0 = sX[ty * 4 + 0][k];
        float b1 = sX[ty * 4 + 1][k];
        float b2 = sX[ty * 4 + 2][k];
        float b3 = sX[ty * 4 + 3][k];
        acc[0][0] += b0 * bv.x; acc[0][1] += b0 * bv.y; acc[0][2] += b0 * bv.z; acc[0][3] += b0 * bv.w;
        acc[1][0] += b1 * bv.x; acc[1][1] += b1 * bv.y; acc[1][2] += b1 * bv.z; acc[1][3] += b1 * bv.w;
        acc[2][0] += b2 * bv.x; acc[2][1] += b2 * bv.y; acc[2][2] += b2 * bv.z; acc[2][3] += b2 * bv.w;
        acc[3][0] += b3 * bv.x; acc[3][1] += b3 * bv.y; acc[3][2] += b3 * bv.z; acc[3][3] += b3 * bv.w;
    }

    float4 bb = *(const float4*)&brel[tx * 4];
    #pragma unroll
    for (int i = 0; i < 4; ++i) {
        int g = rowBase + ty * 4 + i;
        if (g < N_NODES) {
            float4 o;
            o.x = acc[i][0] + bb.x;
            o.y = acc[i][1] + bb.y;
            o.z = acc[i][2] + bb.z;
            o.w = acc[i][3] + bb.w;
            if (do_relu) {
                o.x = fmaxf(o.x, 0.f); o.y = fmaxf(o.y, 0.f);
                o.z = fmaxf(o.z, 0.f); o.w = fmaxf(o.w, 0.f);
            }
            *(float4*)(out + (size_t)g * DH + tx * 4) = o;
            if (outb) {
                __nv_bfloat162 p0 = __float22bfloat162_rn(make_float2(o.x, o.y));
                __nv_bfloat162 p1 = __float22bfloat162_rn(make_float2(o.z, o.w));
                uint2 pk;
                pk.x = ((unsigned)__bfloat16_as_ushort(p0.y) << 16) | __bfloat16_as_ushort(p0.x);
                pk.y = ((unsigned)__bfloat16_as_ushort(p1.y) << 16) | __bfloat16_as_ushort(p1.x);
                *(uint2*)((char*)outb + (size_t)g * 128 + tx * 8) = pk;
            }
        }
    }
}

// ---- P1[g] = sum over edges of graph g of h2b[src] (bf16 reads) ----
__global__ void p1_k(const uint4* __restrict__ Hb,
                     const int* __restrict__ csr,
                     const int* __restrict__ roff,
                     const int* __restrict__ nb,
                     float* __restrict__ P1) {
    int g = blockIdx.x >> 2, part = blockIdx.x & 3;
    int ns = __ldg(&nb[g]), neE = __ldg(&nb[g + 1]);
    int es = __ldg(&roff[ns]), ee = __ldg(&roff[neE]);
    long long len = ee - es;
    int start = es + (int)((len * part) >> 2);
    int end = es + (int)((len * (part + 1)) >> 2);
    int grp = threadIdx.x >> 3;   // 0..31
    int c = threadIdx.x & 7;
    float a0 = 0.f, a1 = 0.f, a2 = 0.f, a3 = 0.f;
    float a4 = 0.f, a5 = 0.f, a6 = 0.f, a7 = 0.f;
    int j = start + grp;
    for (; j + 32 < end; j += 64) {
        int s0 = __ldg(&csr[j]);
        int s1 = __ldg(&csr[j + 32]);
        uint4 v0 = __ldg(&Hb[(size_t)s0 * 8 + c]);
        uint4 v1 = __ldg(&Hb[(size_t)s1 * 8 + c]);
        ACC8(v0); ACC8(v1);
    }
    for (; j < end; j += 32) {
        int s0 = __ldg(&csr[j]);
        uint4 v0 = __ldg(&Hb[(size_t)s0 * 8 + c]);
        ACC8(v0);
    }
    __shared__ float sRed[32][72];
    *(float4*)&sRed[grp][c * 8]     = make_float4(a0, a1, a2, a3);
    *(float4*)&sRed[grp][c * 8 + 4] = make_float4(a4, a5, a6, a7);
    __syncthreads();
    if (threadIdx.x < 16) {
        int q = threadIdx.x;
        float4 s = make_float4(0.f, 0.f, 0.f, 0.f);
        #pragma unroll
        for (int t = 0; t < 32; ++t) {
            float4 v = *(float4*)&sRed[t][q * 4];
            s.x += v.x; s.y += v.y; s.z += v.z; s.w += v.w;
        }
        float* dst = P1 + g * DH + q * 4;
        asm volatile("red.global.add.v4.f32 [%0], {%1,%2,%3,%4};"
                     :: "l"(dst), "f"(s.x), "f"(s.y), "f"(s.z), "f"(s.w)
                     : "memory");
    }
}

// ---- P2[g] = sum over nodes of graph g of h2 (fp32, exact) ----
__global__ void pool2_k(const float* __restrict__ H,
                        const int* __restrict__ nb,
                        float* __restrict__ P2) {
    int g = blockIdx.x;
    int s = __ldg(&nb[g]), e = __ldg(&nb[g + 1]);
    int grp = threadIdx.x >> 4, lane = threadIdx.x & 15;
    const float4* H4 = (const float4*)H;
    float4 acc = make_float4(0.f, 0.f, 0.f, 0.f);
    for (int r = s + grp; r < e; r += 16) {
        float4 v = __ldg(&H4[(size_t)r * 16 + lane]);
        acc.x += v.x; acc.y += v.y; acc.z += v.z; acc.w += v.w;
    }
    __shared__ float sRed[16][68];
    *(float4*)&sRed[grp][lane * 4] = acc;
    __syncthreads();
    if (threadIdx.x < 16) {
        int q = threadIdx.x;
        float4 sv = make_float4(0.f, 0.f, 0.f, 0.f);
        #pragma unroll
        for (int t = 0; t < 16; ++t) {
            float4 v = *(float4*)&sRed[t][q * 4];
            sv.x += v.x; sv.y += v.y; sv.z += v.z; sv.w += v.w;
        }
        *(float4*)&P2[g * DH + q * 4] = sv;
    }
}

// ---- finale ----
__global__ void finale_k(const float* __restrict__ P1,
                         const float* __restrict__ P2,
                         const int* __restrict__ nb,
                         const float* __restrict__ Wrel,
                         const float* __restrict__ brel,
                         const float* __restrict__ Wroot,
                         const float* __restrict__ Wlin,
                         const float* __restrict__ blin,
                         float* __restrict__ out) {
    int g = blockIdx.x;
    int c = threadIdx.x;
    __shared__ float st[64];
    float cnt = fmaxf((float)(nb[g + 1] - nb[g]), 1.0f);
    float t = 0.f;
    #pragma unroll 8
    for (int k = 0; k < 64; ++k)
        t += P1[g * DH + k] * Wrel[k * DH + c] + P2[g * DH + k] * Wroot[k * DH + c];
    st[c] = t / cnt + brel[c];
    __syncthreads();
    if (c < DOUT) {
        float o = blin[c];
        #pragma unroll 8
        for (int k = 0; k < 64; ++k)
            o += st[k] * Wlin[k * DOUT + c];
        out[g * DOUT + c] = o;
    }
}

extern "C" void kernel_launch(void* const* d_in, const int* in_sizes, int n_in,
                              void* d_out, int out_size) {
    const float* x      = (const float*)d_in[0];
    const int*   ei     = (const int*)d_in[1];
    const int*   batch  = (const int*)d_in[3];
    const float* Wrel1  = (const float*)d_in[4];
    const float* brel1  = (const float*)d_in[5];
    const float* Wroot1 = (const float*)d_in[6];
    const float* Wrel2  = (const float*)d_in[7];
    const float* brel2  = (const float*)d_in[8];
    const float* Wroot2 = (const float*)d_in[9];
    const float* Wrel3  = (const float*)d_in[10];
    const float* brel3  = (const float*)d_in[11];
    const float* Wroot3 = (const float*)d_in[12];
    const float* Wlin   = (const float*)d_in[13];
    const float* blin   = (const float*)d_in[14];
    float* out = (float*)d_out;

    int ne = in_sizes[1] / 2;

    void *h1_p, *h2_p, *xb_p, *h1b_p, *h2b_p, *deg_p, *roff_p, *cur_p, *csr_p,
         *p1_p, *p2_p, *nb_p, *bs_p;
    cudaGetSymbolAddress(&h1_p, g_h1);
    cudaGetSymbolAddress(&h2_p, g_h2);
    cudaGetSymbolAddress(&xb_p, g_xb);
    cudaGetSymbolAddress(&h1b_p, g_h1b);
    cudaGetSymbolAddress(&h2b_p, g_h2b);
    cudaGetSymbolAddress(&deg_p, g_deg);
    cudaGetSymbolAddress(&roff_p, g_roff);
    cudaGetSymbolAddress(&cur_p, g_cur);
    cudaGetSymbolAddress(&csr_p, g_csr);
    cudaGetSymbolAddress(&p1_p, g_P1);
    cudaGetSymbolAddress(&p2_p, g_P2);
    cudaGetSymbolAddress(&nb_p, g_nb);
    cudaGetSymbolAddress(&bs_p, g_bsum);

    float* h1 = (float*)h1_p;
    float* h2 = (float*)h2_p;
    uint4* xb = (uint4*)xb_p;
    uint4* h1b = (uint4*)h1b_p;
    uint4* h2b = (uint4*)h2b_p;
    int* deg = (int*)deg_p;
    int* roff = (int*)roff_p;
    int* cur = (int*)cur_p;
    int* csr = (int*)csr_p;
    float* P1 = (float*)p1_p;
    float* P2 = (float*)p2_p;
    int* nb = (int*)nb_p;
    int* bsum = (int*)bs_p;

    static int attr_set = 0;
    if (!attr_set) {
        cudaFuncSetAttribute(layer_k,
                             cudaFuncAttributeMaxDynamicSharedMemorySize, LAYER_SMEM);
        attr_set = 1;
    }

    int edgeBlocks = (ne + 255) / 256;
    int gemmBlocks = (N_NODES + 63) / 64;

    // launch 0: memset deg
    cudaMemsetAsync(deg, 0, N_NODES * sizeof(int), 0);
    // 1: hist + bounds + x->bf16
    hist_bounds_k<<<edgeBlocks, 256>>>(ei, ne, deg, batch, nb, x,
                                       (__nv_bfloat162*)xb);
    // 2-3: scan
    s1_k<<<SCAN_BLOCKS, 1024>>>(deg, bsum);
    s3_k<<<SCAN_BLOCKS, 1024>>>(deg, bsum, roff, cur);
    // 4: fill
    fill_k<<<edgeBlocks, 256>>>(ei, ne, cur, csr);

    // 5-6: layers (launch 5 = layer1, lands in ncu capture slot)
    layer_k<<<gemmBlocks, 256, LAYER_SMEM>>>(x,  xb,  csr, roff, Wrel1, brel1, Wroot1,
                                             h1, h1b, 1);
    layer_k<<<gemmBlocks, 256, LAYER_SMEM>>>(h1, h1b, csr, roff, Wrel2, brel2, Wroot2,
                                             h2, h2b, 1);

    // layer 3 folded into pooled space
    cudaMemsetAsync(P1, 0, N_GRAPHS * DH * sizeof(float), 0);
    p1_k<<<N_GRAPHS * 4, 256>>>(h2b, csr, roff, nb, P1);
    pool2_k<<<N_GRAPHS, 256>>>(h2, nb, P2);
    finale_k<<<N_GRAPHS, 64>>>(P1, P2, nb, Wrel3, brel3, Wroot3, Wlin, blin, out);
}